// round 1
// baseline (speedup 1.0000x reference)
#include <cuda_runtime.h>
#include <cuda_bf16.h>

#define N_B    4
#define C_IN   256
#define T_LEN  2048
#define HEADS  8
#define DK     32

// Scratch for projected q,k,v, each laid out [N][256][T] (== [N][H][d][T]).
__device__ float g_q[N_B * C_IN * T_LEN];
__device__ float g_k[N_B * C_IN * T_LEN];
__device__ float g_v[N_B * C_IN * T_LEN];

// ---------------------------------------------------------------------------
// Projection: y[n][o][t] = sum_c W[o][c] * x[n][c][t] for Wq/Wk/Wv.
// Tiled GEMM: BM=64 (out ch), BN=64 (t), BK=32, 256 threads, 4x4 microtile.
// grid = (T/64, 12, N); blockIdx.y selects which W (0..3 Wq, 4..7 Wk, 8..11 Wv)
// and the 64-row slice of it.
// ---------------------------------------------------------------------------
__global__ __launch_bounds__(256) void proj_kernel(
    const float* __restrict__ x,
    const float* __restrict__ Wq,
    const float* __restrict__ Wk,
    const float* __restrict__ Wv)
{
    __shared__ float Ws[32][65];   // [c][o], pad 1 -> conflict-free stores
    __shared__ float Xs[32][64];   // [c][t]

    const int tid = threadIdx.x;
    const int tx  = tid & 15;          // t microtile index
    const int ty  = tid >> 4;          // o microtile index
    const int t0  = blockIdx.x * 64;
    const int by  = blockIdx.y;
    const int n   = blockIdx.z;
    const int wsel = by >> 2;
    const int o0   = (by & 3) * 64;

    const float* W   = (wsel == 0) ? Wq : (wsel == 1) ? Wk : Wv;
    float*       out = (wsel == 0) ? g_q : (wsel == 1) ? g_k : g_v;
    const float* xb  = x + (size_t)n * C_IN * T_LEN;

    float acc[4][4];
    #pragma unroll
    for (int i = 0; i < 4; i++)
        #pragma unroll
        for (int j = 0; j < 4; j++) acc[i][j] = 0.0f;

    for (int c0 = 0; c0 < C_IN; c0 += 32) {
        // Load W tile: 64 (o) x 32 (c); lanes read consecutive c -> coalesced.
        #pragma unroll
        for (int l = 0; l < 8; l++) {
            int e = l * 256 + tid;
            int o = e >> 5;
            int c = e & 31;
            Ws[c][o] = W[(o0 + o) * C_IN + c0 + c];
        }
        // Load X tile: 32 (c) x 64 (t); lanes read consecutive t -> coalesced.
        #pragma unroll
        for (int l = 0; l < 8; l++) {
            int e = l * 256 + tid;
            int c = e >> 6;
            int t = e & 63;
            Xs[c][t] = xb[(size_t)(c0 + c) * T_LEN + t0 + t];
        }
        __syncthreads();

        #pragma unroll
        for (int c = 0; c < 32; c++) {
            float wf[4];
            #pragma unroll
            for (int i = 0; i < 4; i++) wf[i] = Ws[c][ty * 4 + i];
            float4 xv = *(const float4*)&Xs[c][tx * 4];
            float xf[4] = {xv.x, xv.y, xv.z, xv.w};
            #pragma unroll
            for (int i = 0; i < 4; i++)
                #pragma unroll
                for (int j = 0; j < 4; j++)
                    acc[i][j] = fmaf(wf[i], xf[j], acc[i][j]);
        }
        __syncthreads();
    }

    float* ob = out + (size_t)n * C_IN * T_LEN;
    #pragma unroll
    for (int i = 0; i < 4; i++) {
        float4 v = make_float4(acc[i][0], acc[i][1], acc[i][2], acc[i][3]);
        *(float4*)&ob[(size_t)(o0 + ty * 4 + i) * T_LEN + t0 + tx * 4] = v;
    }
}

// ---------------------------------------------------------------------------
// Flash attention, fp32. One thread per query. Key/value tiles of 128 staged
// in smem as [s][d] (stride 36 keeps float4 alignment: 144B rows).
// grid = (T/128, H, N), block = 128 threads.
// ---------------------------------------------------------------------------
#define KT 128

__global__ __launch_bounds__(128) void attn_kernel(float* __restrict__ out)
{
    __shared__ __align__(16) float Ks[KT][36];
    __shared__ __align__(16) float Vs[KT][36];

    const int t = blockIdx.x * KT + threadIdx.x;
    const int h = blockIdx.y;
    const int n = blockIdx.z;

    const size_t base = ((size_t)n * HEADS + h) * DK * T_LEN;
    const float* qb = g_q + base;
    const float* kb = g_k + base;
    const float* vb = g_v + base;

    const float scale = 0.17677669529663689f;  // 1/sqrt(32)

    float qr[DK], o[DK];
    #pragma unroll
    for (int d = 0; d < DK; d++) {
        qr[d] = qb[(size_t)d * T_LEN + t] * scale;  // coalesced over threads
        o[d]  = 0.0f;
    }

    float m = -1e30f, l = 0.0f;

    for (int s0 = 0; s0 < T_LEN; s0 += KT) {
        __syncthreads();
        #pragma unroll
        for (int d = 0; d < DK; d++) {
            Ks[threadIdx.x][d] = kb[(size_t)d * T_LEN + s0 + threadIdx.x];
            Vs[threadIdx.x][d] = vb[(size_t)d * T_LEN + s0 + threadIdx.x];
        }
        __syncthreads();

        #pragma unroll 2
        for (int s = 0; s < KT; s++) {
            // score = q . k[s]  (smem broadcast, float4)
            const float4* kp = (const float4*)&Ks[s][0];
            float sc = 0.0f;
            #pragma unroll
            for (int d4 = 0; d4 < 8; d4++) {
                float4 kv = kp[d4];
                sc = fmaf(qr[d4 * 4 + 0], kv.x, sc);
                sc = fmaf(qr[d4 * 4 + 1], kv.y, sc);
                sc = fmaf(qr[d4 * 4 + 2], kv.z, sc);
                sc = fmaf(qr[d4 * 4 + 3], kv.w, sc);
            }

            const float4* vp = (const float4*)&Vs[s][0];
            if (sc > m) {
                // new max: rescale accumulators, p == 1
                float alpha = __expf(m - sc);
                m = sc;
                l = fmaf(l, alpha, 1.0f);
                #pragma unroll
                for (int d4 = 0; d4 < 8; d4++) {
                    float4 vv = vp[d4];
                    o[d4 * 4 + 0] = fmaf(o[d4 * 4 + 0], alpha, vv.x);
                    o[d4 * 4 + 1] = fmaf(o[d4 * 4 + 1], alpha, vv.y);
                    o[d4 * 4 + 2] = fmaf(o[d4 * 4 + 2], alpha, vv.z);
                    o[d4 * 4 + 3] = fmaf(o[d4 * 4 + 3], alpha, vv.w);
                }
            } else {
                float p = __expf(sc - m);
                l += p;
                #pragma unroll
                for (int d4 = 0; d4 < 8; d4++) {
                    float4 vv = vp[d4];
                    o[d4 * 4 + 0] = fmaf(p, vv.x, o[d4 * 4 + 0]);
                    o[d4 * 4 + 1] = fmaf(p, vv.y, o[d4 * 4 + 1]);
                    o[d4 * 4 + 2] = fmaf(p, vv.z, o[d4 * 4 + 2]);
                    o[d4 * 4 + 3] = fmaf(p, vv.w, o[d4 * 4 + 3]);
                }
            }
        }
    }

    const float inv = 1.0f / l;
    float* ob = out + base;
    #pragma unroll
    for (int d = 0; d < DK; d++)
        ob[(size_t)d * T_LEN + t] = o[d] * inv;   // coalesced over threads
}

// ---------------------------------------------------------------------------
extern "C" void kernel_launch(void* const* d_in, const int* in_sizes, int n_in,
                              void* d_out, int out_size)
{
    const float* x  = (const float*)d_in[0];
    const float* Wq = (const float*)d_in[1];
    const float* Wk = (const float*)d_in[2];
    const float* Wv = (const float*)d_in[3];
    float* out = (float*)d_out;

    dim3 pgrid(T_LEN / 64, 12, N_B);
    proj_kernel<<<pgrid, 256>>>(x, Wq, Wk, Wv);

    dim3 agrid(T_LEN / KT, HEADS, N_B);
    attn_kernel<<<agrid, 128>>>(out);
}

// round 2
// speedup vs baseline: 2.8086x; 2.8086x over previous
#include <cuda_runtime.h>
#include <cuda_fp16.h>

#define N_B    4
#define C_IN   256
#define T_LEN  2048
#define HEADS  8
#define DK     32

// Scratch for projected q,k,v, each laid out [N][256][T] (== [N][H][d][T]).
__device__ float g_q[N_B * C_IN * T_LEN];
__device__ float g_k[N_B * C_IN * T_LEN];
__device__ float g_v[N_B * C_IN * T_LEN];

// ---------------------------------------------------------------------------
// Projection: y[n][o][t] = sum_c W[o][c] * x[n][c][t] for Wq/Wk/Wv. (unchanged)
// ---------------------------------------------------------------------------
__global__ __launch_bounds__(256) void proj_kernel(
    const float* __restrict__ x,
    const float* __restrict__ Wq,
    const float* __restrict__ Wk,
    const float* __restrict__ Wv)
{
    __shared__ float Ws[32][65];
    __shared__ float Xs[32][64];

    const int tid = threadIdx.x;
    const int tx  = tid & 15;
    const int ty  = tid >> 4;
    const int t0  = blockIdx.x * 64;
    const int by  = blockIdx.y;
    const int n   = blockIdx.z;
    const int wsel = by >> 2;
    const int o0   = (by & 3) * 64;

    const float* W   = (wsel == 0) ? Wq : (wsel == 1) ? Wk : Wv;
    float*       out = (wsel == 0) ? g_q : (wsel == 1) ? g_k : g_v;
    const float* xb  = x + (size_t)n * C_IN * T_LEN;

    float acc[4][4];
    #pragma unroll
    for (int i = 0; i < 4; i++)
        #pragma unroll
        for (int j = 0; j < 4; j++) acc[i][j] = 0.0f;

    for (int c0 = 0; c0 < C_IN; c0 += 32) {
        #pragma unroll
        for (int l = 0; l < 8; l++) {
            int e = l * 256 + tid;
            int o = e >> 5;
            int c = e & 31;
            Ws[c][o] = W[(o0 + o) * C_IN + c0 + c];
        }
        #pragma unroll
        for (int l = 0; l < 8; l++) {
            int e = l * 256 + tid;
            int c = e >> 6;
            int t = e & 63;
            Xs[c][t] = xb[(size_t)(c0 + c) * T_LEN + t0 + t];
        }
        __syncthreads();

        #pragma unroll
        for (int c = 0; c < 32; c++) {
            float wf[4];
            #pragma unroll
            for (int i = 0; i < 4; i++) wf[i] = Ws[c][ty * 4 + i];
            float4 xv = *(const float4*)&Xs[c][tx * 4];
            float xf[4] = {xv.x, xv.y, xv.z, xv.w};
            #pragma unroll
            for (int i = 0; i < 4; i++)
                #pragma unroll
                for (int j = 0; j < 4; j++)
                    acc[i][j] = fmaf(wf[i], xf[j], acc[i][j]);
        }
        __syncthreads();
    }

    float* ob = out + (size_t)n * C_IN * T_LEN;
    #pragma unroll
    for (int i = 0; i < 4; i++) {
        float4 v = make_float4(acc[i][0], acc[i][1], acc[i][2], acc[i][3]);
        *(float4*)&ob[(size_t)(o0 + ty * 4 + i) * T_LEN + t0 + tx * 4] = v;
    }
}

// ---------------------------------------------------------------------------
// Tensor-core flash attention.
//   CTA: 64 queries, 4 warps (16 q-rows each). K-tile = 64 keys.
//   QK^T: mma.m16n8k8 tf32 (precision), S kept in log2 domain.
//   P*V : mma.m16n8k16 fp16 (C-layout of S packs directly into A frags).
// grid = (T/64, H, N), block = 128.
// ---------------------------------------------------------------------------
#define QT 64
#define KT 64

__device__ __forceinline__ unsigned f2tf32(float f) {
    unsigned u;
    asm("cvt.rna.tf32.f32 %0, %1;" : "=r"(u) : "f"(f));
    return u;
}
__device__ __forceinline__ float ex2(float x) {
    float y;
    asm("ex2.approx.f32 %0, %1;" : "=f"(y) : "f"(x));
    return y;
}
__device__ __forceinline__ void mma_tf32(float d[4], const unsigned a[4],
                                         unsigned b0, unsigned b1) {
    asm volatile(
        "mma.sync.aligned.m16n8k8.row.col.f32.tf32.tf32.f32 "
        "{%0,%1,%2,%3}, {%4,%5,%6,%7}, {%8,%9}, {%0,%1,%2,%3};"
        : "+f"(d[0]), "+f"(d[1]), "+f"(d[2]), "+f"(d[3])
        : "r"(a[0]), "r"(a[1]), "r"(a[2]), "r"(a[3]), "r"(b0), "r"(b1));
}
__device__ __forceinline__ void mma_f16(float d[4], const unsigned a[4],
                                        unsigned b0, unsigned b1) {
    asm volatile(
        "mma.sync.aligned.m16n8k16.row.col.f32.f16.f16.f32 "
        "{%0,%1,%2,%3}, {%4,%5,%6,%7}, {%8,%9}, {%0,%1,%2,%3};"
        : "+f"(d[0]), "+f"(d[1]), "+f"(d[2]), "+f"(d[3])
        : "r"(a[0]), "r"(a[1]), "r"(a[2]), "r"(a[3]), "r"(b0), "r"(b1));
}
__device__ __forceinline__ unsigned pack_h2(float x, float y) {
    __half2 h = __floats2half2_rn(x, y);
    return *(unsigned*)&h;
}

__global__ __launch_bounds__(128) void attn_kernel(float* __restrict__ out)
{
    // Ks: tf32 bits, [d=32][key=64] stride 72 words -> conflict-free B-frag LDS.
    // Vs: fp16,       [dv=32][key=64] stride 72 halves.
    // Qs: staging / output roundtrip, [q=64][d=32] stride 33.
    __shared__ unsigned Ks[32 * 72];
    __shared__ __half   Vs[32 * 72];
    __shared__ float    Qs[64][33];
    unsigned* Vsu = (unsigned*)Vs;

    const int tid  = threadIdx.x;
    const int warp = tid >> 5;
    const int lane = tid & 31;
    const int g    = lane >> 2;   // row within 8-group / n-index t/4
    const int c    = lane & 3;

    const int t0 = blockIdx.x * QT;
    const int h  = blockIdx.y;
    const int n  = blockIdx.z;

    const size_t base = ((size_t)n * HEADS + h) * DK * T_LEN;
    const float* qb = g_q + base;
    const float* kb = g_k + base;
    const float* vb = g_v + base;

    // Stage Q (transpose to [q][d]) — once per CTA.
    for (int i = tid; i < QT * DK / 4; i += 128) {
        int d  = i >> 4;
        int q4 = (i & 15) * 4;
        float4 v = *(const float4*)&qb[(size_t)d * T_LEN + t0 + q4];
        Qs[q4 + 0][d] = v.x; Qs[q4 + 1][d] = v.y;
        Qs[q4 + 2][d] = v.z; Qs[q4 + 3][d] = v.w;
    }
    __syncthreads();

    // Q fragments (tf32), scale folded with log2(e) so softmax uses ex2.
    const float qscale = 0.17677669529663689f * 1.4426950408889634f;
    const int q0 = warp * 16;
    unsigned aq[4][4];
    #pragma unroll
    for (int kk = 0; kk < 4; kk++) {
        aq[kk][0] = f2tf32(Qs[q0 + g    ][kk * 8 + c    ] * qscale);
        aq[kk][1] = f2tf32(Qs[q0 + g + 8][kk * 8 + c    ] * qscale);
        aq[kk][2] = f2tf32(Qs[q0 + g    ][kk * 8 + c + 4] * qscale);
        aq[kk][3] = f2tf32(Qs[q0 + g + 8][kk * 8 + c + 4] * qscale);
    }

    float O[4][4];
    #pragma unroll
    for (int jn = 0; jn < 4; jn++)
        #pragma unroll
        for (int i = 0; i < 4; i++) O[jn][i] = 0.0f;
    float m0 = -1e30f, m1 = -1e30f, l0 = 0.0f, l1 = 0.0f;

    for (int s0 = 0; s0 < T_LEN; s0 += KT) {
        __syncthreads();
        // Stage K (tf32) and V (fp16): [32][64], float4 global reads.
        for (int i = tid; i < 32 * KT / 4; i += 128) {
            int d  = i >> 4;
            int k4 = (i & 15) * 4;
            float4 kv = *(const float4*)&kb[(size_t)d * T_LEN + s0 + k4];
            Ks[d * 72 + k4 + 0] = f2tf32(kv.x);
            Ks[d * 72 + k4 + 1] = f2tf32(kv.y);
            Ks[d * 72 + k4 + 2] = f2tf32(kv.z);
            Ks[d * 72 + k4 + 3] = f2tf32(kv.w);
            float4 vv = *(const float4*)&vb[(size_t)d * T_LEN + s0 + k4];
            Vsu[(d * 72 + k4) >> 1]     = pack_h2(vv.x, vv.y);
            Vsu[(d * 72 + k4) >> 1 + 0] = Vsu[(d * 72 + k4) >> 1]; // keep
            Vsu[((d * 72 + k4) >> 1) + 1] = pack_h2(vv.z, vv.w);
        }
        __syncthreads();

        // S = Q*K^T : 8 n-blocks x 4 k-steps of m16n8k8 tf32.
        float S[8][4];
        #pragma unroll
        for (int j = 0; j < 8; j++)
            #pragma unroll
            for (int i = 0; i < 4; i++) S[j][i] = 0.0f;

        #pragma unroll
        for (int j = 0; j < 8; j++) {
            #pragma unroll
            for (int kk = 0; kk < 4; kk++) {
                unsigned b0 = Ks[(kk * 8 + c    ) * 72 + j * 8 + g];
                unsigned b1 = Ks[(kk * 8 + c + 4) * 72 + j * 8 + g];
                mma_tf32(S[j], aq[kk], b0, b1);
            }
        }

        // Online softmax (log2 domain). Rows: r0 = q0+g, r1 = q0+g+8.
        float tm0 = -1e30f, tm1 = -1e30f;
        #pragma unroll
        for (int j = 0; j < 8; j++) {
            tm0 = fmaxf(tm0, fmaxf(S[j][0], S[j][1]));
            tm1 = fmaxf(tm1, fmaxf(S[j][2], S[j][3]));
        }
        tm0 = fmaxf(tm0, __shfl_xor_sync(0xffffffffu, tm0, 1));
        tm0 = fmaxf(tm0, __shfl_xor_sync(0xffffffffu, tm0, 2));
        tm1 = fmaxf(tm1, __shfl_xor_sync(0xffffffffu, tm1, 1));
        tm1 = fmaxf(tm1, __shfl_xor_sync(0xffffffffu, tm1, 2));

        float mn0 = fmaxf(m0, tm0), mn1 = fmaxf(m1, tm1);
        float a0 = ex2(m0 - mn0), a1 = ex2(m1 - mn1);
        m0 = mn0; m1 = mn1;

        float rs0 = 0.0f, rs1 = 0.0f;
        #pragma unroll
        for (int j = 0; j < 8; j++) {
            S[j][0] = ex2(S[j][0] - mn0);
            S[j][1] = ex2(S[j][1] - mn0);
            S[j][2] = ex2(S[j][2] - mn1);
            S[j][3] = ex2(S[j][3] - mn1);
            rs0 += S[j][0] + S[j][1];
            rs1 += S[j][2] + S[j][3];
        }
        rs0 += __shfl_xor_sync(0xffffffffu, rs0, 1);
        rs0 += __shfl_xor_sync(0xffffffffu, rs0, 2);
        rs1 += __shfl_xor_sync(0xffffffffu, rs1, 1);
        rs1 += __shfl_xor_sync(0xffffffffu, rs1, 2);
        l0 = l0 * a0 + rs0;
        l1 = l1 * a1 + rs1;

        #pragma unroll
        for (int jn = 0; jn < 4; jn++) {
            O[jn][0] *= a0; O[jn][1] *= a0;
            O[jn][2] *= a1; O[jn][3] *= a1;
        }

        // Pack P -> fp16 A fragments (C layout == A layout for m16n8k16).
        unsigned ap[4][4];
        #pragma unroll
        for (int jp = 0; jp < 4; jp++) {
            ap[jp][0] = pack_h2(S[2 * jp    ][0], S[2 * jp    ][1]);
            ap[jp][1] = pack_h2(S[2 * jp    ][2], S[2 * jp    ][3]);
            ap[jp][2] = pack_h2(S[2 * jp + 1][0], S[2 * jp + 1][1]);
            ap[jp][3] = pack_h2(S[2 * jp + 1][2], S[2 * jp + 1][3]);
        }

        // O += P * V : 4 dv-blocks x 4 k-steps of m16n8k16 fp16.
        #pragma unroll
        for (int jn = 0; jn < 4; jn++) {
            #pragma unroll
            for (int jp = 0; jp < 4; jp++) {
                unsigned b0 = Vsu[(8 * jn + g) * 36 + 8 * jp + c    ];
                unsigned b1 = Vsu[(8 * jn + g) * 36 + 8 * jp + c + 4];
                mma_f16(O[jn], ap[jp], b0, b1);
            }
        }
    }

    // Normalize and write out via smem for coalesced stores.
    float inv0 = 1.0f / l0, inv1 = 1.0f / l1;
    __syncthreads();
    #pragma unroll
    for (int jn = 0; jn < 4; jn++) {
        Qs[q0 + g    ][8 * jn + 2 * c    ] = O[jn][0] * inv0;
        Qs[q0 + g    ][8 * jn + 2 * c + 1] = O[jn][1] * inv0;
        Qs[q0 + g + 8][8 * jn + 2 * c    ] = O[jn][2] * inv1;
        Qs[q0 + g + 8][8 * jn + 2 * c + 1] = O[jn][3] * inv1;
    }
    __syncthreads();

    float* ob = out + base;
    for (int i = tid; i < QT * DK; i += 128) {
        int d = i >> 6;
        int q = i & 63;
        ob[(size_t)d * T_LEN + t0 + q] = Qs[q][d];
    }
}

// ---------------------------------------------------------------------------
extern "C" void kernel_launch(void* const* d_in, const int* in_sizes, int n_in,
                              void* d_out, int out_size)
{
    const float* x  = (const float*)d_in[0];
    const float* Wq = (const float*)d_in[1];
    const float* Wk = (const float*)d_in[2];
    const float* Wv = (const float*)d_in[3];
    float* out = (float*)d_out;

    dim3 pgrid(T_LEN / 64, 12, N_B);
    proj_kernel<<<pgrid, 256>>>(x, Wq, Wk, Wv);

    dim3 agrid(T_LEN / QT, HEADS, N_B);
    attn_kernel<<<agrid, 128>>>(out);
}